// round 14
// baseline (speedup 1.0000x reference)
#include <cuda_runtime.h>
#include <cuda_fp16.h>
#include <cstdint>

// Problem constants (B=64, S=1024, D=768, R=4)
#define DD    768
#define ND    2304
#define RR    4
#define MTOT  65536

// GEMM tiling
#define BM 128
#define BN 128
#define BK 32
#define NKT (DD / BK)        // 24
#define STAGES 4

// smem stage layout: padded rows of 40 halves (80 B) for conflict-free ldmatrix
#define ROWB   80
#define MAT_B  (128 * ROWB)  // 10240 bytes per matrix tile
#define A_T    0
#define B_T    (MAT_B)
#define STG    (2 * MAT_B)   // 20480
#define SMEM_TOTAL (STAGES * STG)  // 81920

// fused prep kernel: grid-stride workers
#define CONV_BLKS 1024
#define FOLD_BLKS 96
#define PREP_THREADS 256
#define NF4 (MTOT * DD / 4)            // 12,582,912 float4 elements in X

// Static device scratch (no runtime allocation allowed)
__device__ __align__(128) __half g_X[(size_t)MTOT * DD];
__device__ __align__(128) __half g_W[(size_t)ND * DD];

// ---------------------------------------------------------------------------
// PTX helpers (baseline ISA only — safe under compute_103 virtual arch)
// ---------------------------------------------------------------------------
__device__ __forceinline__ uint32_t smem_u32(const void* p) {
    uint32_t a;
    asm("{ .reg .u64 t; cvta.to.shared.u64 t, %1; cvt.u32.u64 %0, t; }"
        : "=r"(a) : "l"(p));
    return a;
}

#define CPA(saddr, gaddr) \
    asm volatile("cp.async.cg.shared.global [%0], [%1], 16;" \
                 :: "r"(saddr), "l"(gaddr))

#define CP_COMMIT() asm volatile("cp.async.commit_group;" ::: "memory")
#define CP_WAIT2()  asm volatile("cp.async.wait_group 2;" ::: "memory")

#define LDSM4(r, addr)                                                        \
    asm volatile("ldmatrix.sync.aligned.m8n8.x4.shared.b16 {%0,%1,%2,%3}, [%4];" \
                 : "=r"((r)[0]), "=r"((r)[1]), "=r"((r)[2]), "=r"((r)[3])     \
                 : "r"(addr))

#define MMA(c, a, b0, b1)                                                     \
    asm volatile("mma.sync.aligned.m16n8k16.row.col.f32.f16.f16.f32 "         \
                 "{%0,%1,%2,%3},{%4,%5,%6,%7},{%8,%9},{%0,%1,%2,%3};"         \
                 : "+f"((c)[0]), "+f"((c)[1]), "+f"((c)[2]), "+f"((c)[3])     \
                 : "r"((a)[0]), "r"((a)[1]), "r"((a)[2]), "r"((a)[3]),        \
                   "r"(b0), "r"(b1))

// ---------------------------------------------------------------------------
// Kernel 0 (fused prep, grid-stride):
//   blocks [0, CONV_BLKS): X fp32 -> fp16 (4 float4 per thread per iter)
//   blocks [CONV_BLKS, +FOLD_BLKS): LoRA-fold W -> fp16
// ---------------------------------------------------------------------------
__global__ void __launch_bounds__(PREP_THREADS) prep(
                     const float4* __restrict__ X,
                     const float* __restrict__ W,
                     const float* __restrict__ Aq, const float* __restrict__ Bq,
                     const float* __restrict__ Av, const float* __restrict__ Bv,
                     const float* __restrict__ s0p) {
    if (blockIdx.x < CONV_BLKS) {
        // 4 float4 per thread per iteration, batched for MLP
        const size_t stride = (size_t)CONV_BLKS * PREP_THREADS * 4;
        for (size_t base = ((size_t)blockIdx.x * PREP_THREADS + threadIdx.x) * 4;
             base < NF4; base += stride) {
            float4 v0 = X[base + 0];
            float4 v1 = X[base + 1];
            float4 v2 = X[base + 2];
            float4 v3 = X[base + 3];
            __half2 h[8];
            h[0] = __floats2half2_rn(v0.x, v0.y);
            h[1] = __floats2half2_rn(v0.z, v0.w);
            h[2] = __floats2half2_rn(v1.x, v1.y);
            h[3] = __floats2half2_rn(v1.z, v1.w);
            h[4] = __floats2half2_rn(v2.x, v2.y);
            h[5] = __floats2half2_rn(v2.z, v2.w);
            h[6] = __floats2half2_rn(v3.x, v3.y);
            h[7] = __floats2half2_rn(v3.z, v3.w);
            uint4* po = reinterpret_cast<uint4*>(g_X) + base / 2;
            const uint32_t* hw = reinterpret_cast<const uint32_t*>(h);
            po[0] = make_uint4(hw[0], hw[1], hw[2], hw[3]);
            po[1] = make_uint4(hw[4], hw[5], hw[6], hw[7]);
        }
    } else {
        const int stride = FOLD_BLKS * PREP_THREADS;
        const float s = s0p[0];
        for (int idx = (blockIdx.x - CONV_BLKS) * PREP_THREADS + threadIdx.x;
             idx < ND * DD; idx += stride) {
            int e = idx / DD;
            int d = idx - e * DD;
            float v = W[idx];
            if (e < DD) {
                float acc = 0.f;
#pragma unroll
                for (int r = 0; r < RR; r++)
                    acc = fmaf(Bq[e * RR + r], Aq[r * DD + d], acc);
                v = fmaf(s, acc, v);
            } else if (e >= 2 * DD) {
                int e2 = e - 2 * DD;
                float acc = 0.f;
#pragma unroll
                for (int r = 0; r < RR; r++)
                    acc = fmaf(Bv[e2 * RR + r], Av[r * DD + d], acc);
                v = fmaf(s, acc, v);
            }
            g_W[idx] = __float2half(v);
        }
    }
}

// ---------------------------------------------------------------------------
// Kernel 1: fp16 mma.sync GEMM, single term, fp32 accumulate.  (R13-exact)
//   Out[M, ND] = X @ W^T + bias
//   128x128x32 CTA tile, 8 warps (2x4), 64x32 warp tile, 4-stage cp.async.
//   ONE barrier per k-chunk; cp.async issued under the kk0 LDSM shadow.
//   2 CTAs/SM (80 KB smem each).
// ---------------------------------------------------------------------------
__global__ void __launch_bounds__(256, 2) gemm_mma(
    const float* __restrict__ bias, float* __restrict__ Out) {
    extern __shared__ char smem[];
    const uint32_t sb = smem_u32(smem);

    const int tid  = threadIdx.x;
    const int wid  = tid >> 5;
    const int lane = tid & 31;
    const int wm   = wid >> 2;          // 0..1  (64 rows each)
    const int wn   = wid & 3;           // 0..3  (32 cols each)
    const int n0   = blockIdx.x * BN;
    const int m0   = blockIdx.y * BM;

    // global load mapping: 512 16B chunks per matrix tile, 2 per thread
    const int r0c = tid >> 2;           // row for chunk 0 (0..63)
    const int cc  = tid & 3;            // 16B column (0..3)

    float acc[4][4][4];
#pragma unroll
    for (int i = 0; i < 4; i++)
#pragma unroll
        for (int j = 0; j < 4; j++)
#pragma unroll
            for (int q = 0; q < 4; q++) acc[i][j][q] = 0.f;

    // ---- stage loader ----
    auto load_stage = [&](int kt, int buf) {
        const uint32_t st = sb + buf * STG;
#pragma unroll
        for (int i = 0; i < 2; i++) {
            const int row = r0c + i * 64;
            const uint32_t so = st + row * ROWB + cc * 16;
            const size_t ga = (size_t)(m0 + row) * DD + kt * BK + cc * 8;
            const size_t gb = (size_t)(n0 + row) * DD + kt * BK + cc * 8;
            CPA(so + A_T, (const char*)(g_X + ga));
            CPA(so + B_T, (const char*)(g_W + gb));
        }
    };

    load_stage(0, 0); CP_COMMIT();
    load_stage(1, 1); CP_COMMIT();
    load_stage(2, 2); CP_COMMIT();

    // per-lane ldmatrix address pieces
    const int lrow = lane & 15;
    const int lhal = (lane >> 4) << 4;  // 0 or 16 bytes (8-col half)

    for (int kt = 0; kt < NKT; kt++) {
        const int buf = kt % STAGES;
        CP_WAIT2();
        __syncthreads();        // single barrier per k-chunk

        const uint32_t st = sb + buf * STG;
        const uint32_t abase = st + (wm * 64 + lrow) * ROWB + lhal;
        const uint32_t bbase = st + (wn * 32 + lrow) * ROWB + lhal;

        // ---- kk = 0: LDSM, then next-stage loads under their shadow ----
        uint32_t aw[4][4], bw[2][4];
#pragma unroll
        for (int ti = 0; ti < 4; ti++)
            LDSM4(aw[ti], abase + A_T + ti * (16 * ROWB));
#pragma unroll
        for (int tj = 0; tj < 2; tj++)
            LDSM4(bw[tj], bbase + B_T + tj * (16 * ROWB));

        if (kt + 3 < NKT) load_stage(kt + 3, (kt + 3) % STAGES);
        CP_COMMIT();

#pragma unroll
        for (int ti = 0; ti < 4; ti++) {
#pragma unroll
            for (int nj = 0; nj < 4; nj++) {
                const int tj = nj >> 1, o = nj & 1;
                MMA(acc[ti][nj], aw[ti], bw[tj][o], bw[tj][o + 2]);
            }
        }

        // ---- kk = 1: LDSM overlaps kk0 MMA drain ----
#pragma unroll
        for (int ti = 0; ti < 4; ti++)
            LDSM4(aw[ti], abase + A_T + ti * (16 * ROWB) + 32);
#pragma unroll
        for (int tj = 0; tj < 2; tj++)
            LDSM4(bw[tj], bbase + B_T + tj * (16 * ROWB) + 32);

#pragma unroll
        for (int ti = 0; ti < 4; ti++) {
#pragma unroll
            for (int nj = 0; nj < 4; nj++) {
                const int tj = nj >> 1, o = nj & 1;
                MMA(acc[ti][nj], aw[ti], bw[tj][o], bw[tj][o + 2]);
            }
        }
        // no bottom barrier
    }

    // ---- epilogue: bias + store ----
    const int orow_base = m0 + wm * 64 + (lane >> 2);
    const int ocol_base = n0 + wn * 32 + (lane & 3) * 2;
#pragma unroll
    for (int ti = 0; ti < 4; ti++) {
        const int r0 = orow_base + ti * 16;
#pragma unroll
        for (int nj = 0; nj < 4; nj++) {
            const int c = ocol_base + nj * 8;
            const float2 bs = *reinterpret_cast<const float2*>(bias + c);
            float2 v0, v1;
            v0.x = acc[ti][nj][0] + bs.x;
            v0.y = acc[ti][nj][1] + bs.y;
            v1.x = acc[ti][nj][2] + bs.x;
            v1.y = acc[ti][nj][3] + bs.y;
            *reinterpret_cast<float2*>(Out + (size_t)r0 * ND + c) = v0;
            *reinterpret_cast<float2*>(Out + (size_t)(r0 + 8) * ND + c) = v1;
        }
    }
}

// ---------------------------------------------------------------------------
// Launch.  Inputs (metadata order): x, W_qkv, b_qkv, A_q, B_q, A_v, B_v, s0
// ---------------------------------------------------------------------------
extern "C" void kernel_launch(void* const* d_in, const int* in_sizes, int n_in,
                              void* d_out, int out_size) {
    const float* x  = (const float*)d_in[0];
    const float* W  = (const float*)d_in[1];
    const float* b  = (const float*)d_in[2];
    const float* Aq = (const float*)d_in[3];
    const float* Bq = (const float*)d_in[4];
    const float* Av = (const float*)d_in[5];
    const float* Bv = (const float*)d_in[6];
    const float* s0 = (const float*)d_in[7];
    float* out = (float*)d_out;

    prep<<<CONV_BLKS + FOLD_BLKS, PREP_THREADS>>>(
        (const float4*)x, W, Aq, Bq, Av, Bv, s0);

    static bool attr_set = false;
    if (!attr_set) {
        cudaFuncSetAttribute(gemm_mma,
                             cudaFuncAttributeMaxDynamicSharedMemorySize,
                             SMEM_TOTAL);
        attr_set = true;
    }
    dim3 grid(ND / BN, MTOT / BM);      // (18, 512); x-fast => X tile L2 reuse
    gemm_mma<<<grid, 256, SMEM_TOTAL>>>(b, out);
}

// round 17
// speedup vs baseline: 1.0442x; 1.0442x over previous
#include <cuda_runtime.h>
#include <cuda_fp16.h>
#include <cstdint>

// Problem constants (B=64, S=1024, D=768, R=4)
#define DD    768
#define ND    2304
#define RR    4
#define MTOT  65536

// GEMM tiling
#define BM 128
#define BN 128
#define BK 32
#define NKT (DD / BK)        // 24
#define STAGES 4

// smem stage layout: padded rows of 40 halves (80 B) for conflict-free ldmatrix
#define ROWB   80
#define MAT_B  (128 * ROWB)  // 10240 bytes per matrix tile
#define A_T    0
#define B_T    (MAT_B)
#define STG    (2 * MAT_B)   // 20480
#define SMEM_TOTAL (STAGES * STG)  // 81920

// M-split pipeline
#define NSPLIT  8
#define MBLKS   (MTOT / BM)            // 512 m-blocks
#define MBLKS_SPLIT (MBLKS / NSPLIT)   // 64 per split
#define NF4     (MTOT * DD / 4)        // 12,582,912 float4 in X
#define NF4_SPLIT (NF4 / NSPLIT)       // 1,572,864
#define CONV_BLKS_SPLIT (NF4_SPLIT / 256)  // 6144
#define FOLD_BLKS ((ND * DD + 255) / 256)  // 6912

// Static device scratch (no runtime allocation allowed)
__device__ __align__(128) __half g_X[(size_t)MTOT * DD];
__device__ __align__(128) __half g_W[(size_t)ND * DD];

// ---------------------------------------------------------------------------
// PTX helpers (baseline ISA only — safe under compute_103 virtual arch)
// ---------------------------------------------------------------------------
__device__ __forceinline__ uint32_t smem_u32(const void* p) {
    uint32_t a;
    asm("{ .reg .u64 t; cvta.to.shared.u64 t, %1; cvt.u32.u64 %0, t; }"
        : "=r"(a) : "l"(p));
    return a;
}

#define CPA(saddr, gaddr) \
    asm volatile("cp.async.cg.shared.global [%0], [%1], 16;" \
                 :: "r"(saddr), "l"(gaddr))

#define CP_COMMIT() asm volatile("cp.async.commit_group;" ::: "memory")
#define CP_WAIT2()  asm volatile("cp.async.wait_group 2;" ::: "memory")

#define LDSM4(r, addr)                                                        \
    asm volatile("ldmatrix.sync.aligned.m8n8.x4.shared.b16 {%0,%1,%2,%3}, [%4];" \
                 : "=r"((r)[0]), "=r"((r)[1]), "=r"((r)[2]), "=r"((r)[3])     \
                 : "r"(addr))

#define MMA(c, a, b0, b1)                                                     \
    asm volatile("mma.sync.aligned.m16n8k16.row.col.f32.f16.f16.f32 "         \
                 "{%0,%1,%2,%3},{%4,%5,%6,%7},{%8,%9},{%0,%1,%2,%3};"         \
                 : "+f"((c)[0]), "+f"((c)[1]), "+f"((c)[2]), "+f"((c)[3])     \
                 : "r"((a)[0]), "r"((a)[1]), "r"((a)[2]), "r"((a)[3]),        \
                   "r"(b0), "r"(b1))

// ---------------------------------------------------------------------------
// Kernel 0a: fold LoRA into W (rank-4 update on q and v row blocks) -> fp16
// ---------------------------------------------------------------------------
__global__ void fold_w(const float* __restrict__ W,
                       const float* __restrict__ Aq, const float* __restrict__ Bq,
                       const float* __restrict__ Av, const float* __restrict__ Bv,
                       const float* __restrict__ s0p) {
    int idx = blockIdx.x * blockDim.x + threadIdx.x;
    if (idx >= ND * DD) return;
    int e = idx / DD;
    int d = idx - e * DD;
    float v = W[idx];
    float s = s0p[0];
    if (e < DD) {
        float acc = 0.f;
#pragma unroll
        for (int r = 0; r < RR; r++) acc = fmaf(Bq[e * RR + r], Aq[r * DD + d], acc);
        v = fmaf(s, acc, v);
    } else if (e >= 2 * DD) {
        int e2 = e - 2 * DD;
        float acc = 0.f;
#pragma unroll
        for (int r = 0; r < RR; r++) acc = fmaf(Bv[e2 * RR + r], Av[r * DD + d], acc);
        v = fmaf(s, acc, v);
    }
    g_W[idx] = __float2half(v);
}

// ---------------------------------------------------------------------------
// Kernel 0b: convert one X chunk fp32 -> fp16 (R13 mapping: 1 float4/thread)
// ---------------------------------------------------------------------------
__global__ void conv_x(const float4* __restrict__ X, int f4_base) {
    size_t i = (size_t)f4_base + blockIdx.x * blockDim.x + threadIdx.x;
    float4 v = X[i];
    __half2* ph = reinterpret_cast<__half2*>(g_X) + i * 2;
    ph[0] = __floats2half2_rn(v.x, v.y);
    ph[1] = __floats2half2_rn(v.z, v.w);
}

// ---------------------------------------------------------------------------
// Kernel 1: fp16 mma.sync GEMM, single term, fp32 accumulate.  (R13-exact +
//           m_base for the M-split pipeline)
//   Out[m_base.., ND] = X @ W^T + bias
//   128x128x32 CTA tile, 8 warps (2x4), 64x32 warp tile, 4-stage cp.async.
//   ONE barrier per k-chunk; cp.async issued under the kk0 LDSM shadow.
//   2 CTAs/SM (80 KB smem each).
// ---------------------------------------------------------------------------
__global__ void __launch_bounds__(256, 2) gemm_mma(
    const float* __restrict__ bias, float* __restrict__ Out, int m_base) {
    extern __shared__ char smem[];
    const uint32_t sb = smem_u32(smem);

    const int tid  = threadIdx.x;
    const int wid  = tid >> 5;
    const int lane = tid & 31;
    const int wm   = wid >> 2;          // 0..1  (64 rows each)
    const int wn   = wid & 3;           // 0..3  (32 cols each)
    const int n0   = blockIdx.x * BN;
    const int m0   = (blockIdx.y + m_base) * BM;

    // global load mapping: 512 16B chunks per matrix tile, 2 per thread
    const int r0c = tid >> 2;           // row for chunk 0 (0..63)
    const int cc  = tid & 3;            // 16B column (0..3)

    float acc[4][4][4];
#pragma unroll
    for (int i = 0; i < 4; i++)
#pragma unroll
        for (int j = 0; j < 4; j++)
#pragma unroll
            for (int q = 0; q < 4; q++) acc[i][j][q] = 0.f;

    // ---- stage loader ----
    auto load_stage = [&](int kt, int buf) {
        const uint32_t st = sb + buf * STG;
#pragma unroll
        for (int i = 0; i < 2; i++) {
            const int row = r0c + i * 64;
            const uint32_t so = st + row * ROWB + cc * 16;
            const size_t ga = (size_t)(m0 + row) * DD + kt * BK + cc * 8;
            const size_t gb = (size_t)(n0 + row) * DD + kt * BK + cc * 8;
            CPA(so + A_T, (const char*)(g_X + ga));
            CPA(so + B_T, (const char*)(g_W + gb));
        }
    };

    load_stage(0, 0); CP_COMMIT();
    load_stage(1, 1); CP_COMMIT();
    load_stage(2, 2); CP_COMMIT();

    // per-lane ldmatrix address pieces
    const int lrow = lane & 15;
    const int lhal = (lane >> 4) << 4;  // 0 or 16 bytes (8-col half)

    for (int kt = 0; kt < NKT; kt++) {
        const int buf = kt % STAGES;
        CP_WAIT2();
        __syncthreads();        // single barrier per k-chunk

        const uint32_t st = sb + buf * STG;
        const uint32_t abase = st + (wm * 64 + lrow) * ROWB + lhal;
        const uint32_t bbase = st + (wn * 32 + lrow) * ROWB + lhal;

        // ---- kk = 0: LDSM, then next-stage loads under their shadow ----
        uint32_t aw[4][4], bw[2][4];
#pragma unroll
        for (int ti = 0; ti < 4; ti++)
            LDSM4(aw[ti], abase + A_T + ti * (16 * ROWB));
#pragma unroll
        for (int tj = 0; tj < 2; tj++)
            LDSM4(bw[tj], bbase + B_T + tj * (16 * ROWB));

        if (kt + 3 < NKT) load_stage(kt + 3, (kt + 3) % STAGES);
        CP_COMMIT();

#pragma unroll
        for (int ti = 0; ti < 4; ti++) {
#pragma unroll
            for (int nj = 0; nj < 4; nj++) {
                const int tj = nj >> 1, o = nj & 1;
                MMA(acc[ti][nj], aw[ti], bw[tj][o], bw[tj][o + 2]);
            }
        }

        // ---- kk = 1: LDSM overlaps kk0 MMA drain ----
#pragma unroll
        for (int ti = 0; ti < 4; ti++)
            LDSM4(aw[ti], abase + A_T + ti * (16 * ROWB) + 32);
#pragma unroll
        for (int tj = 0; tj < 2; tj++)
            LDSM4(bw[tj], bbase + B_T + tj * (16 * ROWB) + 32);

#pragma unroll
        for (int ti = 0; ti < 4; ti++) {
#pragma unroll
            for (int nj = 0; nj < 4; nj++) {
                const int tj = nj >> 1, o = nj & 1;
                MMA(acc[ti][nj], aw[ti], bw[tj][o], bw[tj][o + 2]);
            }
        }
        // no bottom barrier
    }

    // ---- epilogue: bias + store ----
    const int orow_base = m0 + wm * 64 + (lane >> 2);
    const int ocol_base = n0 + wn * 32 + (lane & 3) * 2;
#pragma unroll
    for (int ti = 0; ti < 4; ti++) {
        const int r0 = orow_base + ti * 16;
#pragma unroll
        for (int nj = 0; nj < 4; nj++) {
            const int c = ocol_base + nj * 8;
            const float2 bs = *reinterpret_cast<const float2*>(bias + c);
            float2 v0, v1;
            v0.x = acc[ti][nj][0] + bs.x;
            v0.y = acc[ti][nj][1] + bs.y;
            v1.x = acc[ti][nj][2] + bs.x;
            v1.y = acc[ti][nj][3] + bs.y;
            *reinterpret_cast<float2*>(Out + (size_t)r0 * ND + c) = v0;
            *reinterpret_cast<float2*>(Out + (size_t)(r0 + 8) * ND + c) = v1;
        }
    }
}

// ---------------------------------------------------------------------------
// Launch.  Inputs (metadata order): x, W_qkv, b_qkv, A_q, B_q, A_v, B_v, s0
//
// Pipeline: conv(j) on the capture stream overlaps GEMM(j-1) on a worker
// stream. GEMMs alternate between two worker streams so each split's CTA
// drain is backfilled by the next split. Fork/join via events (capturable).
// ---------------------------------------------------------------------------
extern "C" void kernel_launch(void* const* d_in, const int* in_sizes, int n_in,
                              void* d_out, int out_size) {
    const float* x  = (const float*)d_in[0];
    const float* W  = (const float*)d_in[1];
    const float* b  = (const float*)d_in[2];
    const float* Aq = (const float*)d_in[3];
    const float* Bq = (const float*)d_in[4];
    const float* Av = (const float*)d_in[5];
    const float* Bv = (const float*)d_in[6];
    const float* s0 = (const float*)d_in[7];
    float* out = (float*)d_out;

    static cudaStream_t sA = nullptr, sB = nullptr;
    static cudaEvent_t ev[NSPLIT], evj[2];
    static bool init_done = false;
    if (!init_done) {
        cudaFuncSetAttribute(gemm_mma,
                             cudaFuncAttributeMaxDynamicSharedMemorySize,
                             SMEM_TOTAL);
        cudaStreamCreateWithFlags(&sA, cudaStreamNonBlocking);
        cudaStreamCreateWithFlags(&sB, cudaStreamNonBlocking);
        for (int j = 0; j < NSPLIT; j++)
            cudaEventCreateWithFlags(&ev[j], cudaEventDisableTiming);
        cudaEventCreateWithFlags(&evj[0], cudaEventDisableTiming);
        cudaEventCreateWithFlags(&evj[1], cudaEventDisableTiming);
        init_done = true;
    }

    // Prep chain on the capture (default) stream. fold_w first (needed by all
    // GEMM splits; ordered before every ev[j] by stream order).
    fold_w<<<FOLD_BLKS, 256>>>(W, Aq, Bq, Av, Bv, s0);
    for (int j = 0; j < NSPLIT; j++) {
        conv_x<<<CONV_BLKS_SPLIT, 256>>>((const float4*)x, j * NF4_SPLIT);
        cudaEventRecord(ev[j], 0);
    }

    // GEMM splits on alternating worker streams, each gated on its prep chunk.
    dim3 grid(ND / BN, MBLKS_SPLIT);    // (18, 64)
    for (int j = 0; j < NSPLIT; j++) {
        cudaStream_t s = (j & 1) ? sB : sA;
        cudaStreamWaitEvent(s, ev[j], 0);
        gemm_mma<<<grid, 256, SMEM_TOTAL, s>>>(b, out, j * MBLKS_SPLIT);
    }

    // Join back into the capture stream.
    cudaEventRecord(evj[0], sA);
    cudaEventRecord(evj[1], sB);
    cudaStreamWaitEvent(0, evj[0], 0);
    cudaStreamWaitEvent(0, evj[1], 0);
}